// round 15
// baseline (speedup 1.0000x reference)
#include <cuda_runtime.h>
#include <cuda_fp16.h>
#include <math.h>
#include <stdint.h>

#define Bn   256
#define Hn   1024
#define XDn  192
#define YDn  64
#define INn  256
#define PREn 64
#define FWDn 48
#define G4H  4096

// ---------------- scratch (device globals; no allocations allowed) ----------
__device__ __half g_W0h[G4H * 1280], g_W0l[G4H * 1280];
__device__ __half g_W1h[G4H * 2048], g_W1l[G4H * 2048];
__device__ __half g_Wfh[Hn * Hn],    g_Wfl[Hn * Hn];
__device__ float  g_bp0[G4H], g_bp1[G4H];
__device__ __half g_XYh[PREn * Bn * INn], g_XYl[PREn * Bn * INn];
__device__ __half g_FXh[FWDn * Bn * INn], g_FXl[FWDn * Bn * INn];
__device__ __half g_H0h[2][Bn * Hn], g_H0l[2][Bn * Hn];
__device__ __half g_H1h[2][Bn * Hn], g_H1l[2][Bn * Hn];
__device__ float g_c0[Bn * Hn], g_c1[Bn * Hn];
__device__ float g_t1p[4][Bn * Hn], g_est[Bn * YDn];
__device__ unsigned g_fccnt[FWDn];        // fc-group GEMM-done barrier
__device__ unsigned g_fcdone[FWDn];       // fccomb (est written) barrier

// ---------------- helpers ----------------------------------------------------
__device__ __forceinline__ float sigf(float x) { return 1.0f / (1.0f + expf(-x)); }

__device__ __forceinline__ void cpa16(void* dst, const void* src) {
    unsigned d = (unsigned)__cvta_generic_to_shared(dst);
    asm volatile("cp.async.cg.shared.global [%0], [%1], 16;\n" :: "r"(d), "l"(src));
}

__device__ __forceinline__ void ldsm_x4(unsigned r[4], const unsigned* p) {
    unsigned addr = (unsigned)__cvta_generic_to_shared(p);
    asm volatile("ldmatrix.sync.aligned.m8n8.x4.shared.b16 {%0,%1,%2,%3}, [%4];\n"
        : "=r"(r[0]), "=r"(r[1]), "=r"(r[2]), "=r"(r[3]) : "r"(addr));
}

// fp32-accumulate HMMA (hi*hi term)
__device__ __forceinline__ void mma16816(float c[4], const unsigned a[4], const unsigned b[2]) {
    asm volatile(
        "mma.sync.aligned.m16n8k16.row.col.f32.f16.f16.f32 "
        "{%0,%1,%2,%3}, {%4,%5,%6,%7}, {%8,%9}, {%0,%1,%2,%3};\n"
        : "+f"(c[0]), "+f"(c[1]), "+f"(c[2]), "+f"(c[3])
        : "r"(a[0]), "r"(a[1]), "r"(a[2]), "r"(a[3]), "r"(b[0]), "r"(b[1]));
}

// fp16-accumulate HMMA (correction terms)
__device__ __forceinline__ void mma16816h(unsigned c[2], const unsigned a[4], const unsigned b[2]) {
    asm volatile(
        "mma.sync.aligned.m16n8k16.row.col.f16.f16.f16.f16 "
        "{%0,%1}, {%2,%3,%4,%5}, {%6,%7}, {%0,%1};\n"
        : "+r"(c[0]), "+r"(c[1])
        : "r"(a[0]), "r"(a[1]), "r"(a[2]), "r"(a[3]), "r"(b[0]), "r"(b[1]));
}

__device__ __forceinline__ float2 h2f2(unsigned u) {
    __half2 h = *reinterpret_cast<__half2*>(&u);
    return __half22float2(h);
}

// ---------------- fp16x3 GEMM core: 64x128, 3-stage (round-7 structure) -----
#define BM 64
#define BN 128
#define BK 32
#define RS 20
#define OFF_AH 0
#define OFF_AL (BM * RS)
#define OFF_WH (2 * BM * RS)
#define OFF_WL (2 * BM * RS + BN * RS)
#define STAGE  (2 * BM * RS + 2 * BN * RS)   // 7680 uints = 30720 B
#define NSTG   3
#define SMEMB  (NSTG * STAGE * 4)            // 92160 B

__device__ __forceinline__ void load_tile(
    unsigned* sm, int sbase, int k0, int m0, int n0, int tid,
    const __half* a0h, const __half* a0l, int w0, int lda0,
    const __half* a1h, const __half* a1l, int lda1,
    const __half* wgh, const __half* wgl, int ldw)
{
    const __half *ah, *al; int lda, koff;
    if (k0 < w0) { ah = a0h; al = a0l; lda = lda0; koff = k0; }
    else         { ah = a1h; al = a1l; lda = lda1; koff = k0 - w0; }
#pragma unroll
    for (int i = 0; i < 2; i++) {           // A: 512 16B chunks (hi+lo)
        int c = tid + (i << 8);
        int part = c >> 8;
        int row  = (c & 255) >> 2;
        int kc   = c & 3;
        const __half* src = (part ? al : ah) + (size_t)(m0 + row) * lda + koff + kc * 8;
        unsigned* dst = sm + sbase + (part ? OFF_AL : OFF_AH) + row * RS + kc * 4;
        cpa16(dst, src);
    }
#pragma unroll
    for (int i = 0; i < 4; i++) {           // W: 1024 16B chunks (hi+lo)
        int c = tid + (i << 8);
        int part = c >> 9;
        int row  = (c & 511) >> 2;
        int kc   = c & 3;
        const __half* src = (part ? wgl : wgh) + (size_t)(n0 + row) * ldw + k0 + kc * 8;
        unsigned* dst = sm + sbase + (part ? OFF_WL : OFF_WH) + row * RS + kc * 4;
        cpa16(dst, src);
    }
}

// mode 0: fused LSTM cell (gate-interleaved W); mode 2: raw acc -> out2[r*ldo+c]
__device__ __forceinline__ void gemm_core(
    unsigned* sm, int m0, int n0, int kt0, int NT,
    const __half* a0h, const __half* a0l, int w0, int lda0,
    const __half* a1h, const __half* a1l, int lda1,
    const __half* wgh, const __half* wgl, int ldw,
    const float* bias, int mode,
    float* out2, int ldo,
    float* cst, __half* Hh, __half* Hl)
{
    const int tid  = threadIdx.x;
    const int warp = tid >> 5;
    const int lane = tid & 31;
    const int wm = (warp & 1) * 32;
    const int wn = (warp >> 1) * 32;
    const int gr = lane >> 2;
    const int tg = lane & 3;
    const int a_row  = wm + (lane & 15);
    const int a_colu = (lane >> 4) << 2;
    const int b_row  = wn + (lane & 7) + ((lane >> 4) << 3);
    const int b_colu = ((lane >> 3) & 1) << 2;

    float acc[2][4][4];
    unsigned cacc[2][4][2];
#pragma unroll
    for (int mi = 0; mi < 2; mi++)
#pragma unroll
        for (int ni = 0; ni < 4; ni++) {
#pragma unroll
            for (int e = 0; e < 4; e++) acc[mi][ni][e] = 0.0f;
            cacc[mi][ni][0] = 0u; cacc[mi][ni][1] = 0u;
        }

    load_tile(sm, 0, kt0 * BK, m0, n0, tid, a0h, a0l, w0, lda0, a1h, a1l, lda1, wgh, wgl, ldw);
    asm volatile("cp.async.commit_group;\n");
    if (NT > 1) {
        load_tile(sm, STAGE, (kt0 + 1) * BK, m0, n0, tid, a0h, a0l, w0, lda0, a1h, a1l, lda1, wgh, wgl, ldw);
        asm volatile("cp.async.commit_group;\n");
    }

    for (int i = 0; i < NT; i++) {
        if (i + 2 < NT) {
            load_tile(sm, ((i + 2) % NSTG) * STAGE, (kt0 + i + 2) * BK, m0, n0, tid,
                      a0h, a0l, w0, lda0, a1h, a1l, lda1, wgh, wgl, ldw);
            asm volatile("cp.async.commit_group;\n");
            asm volatile("cp.async.wait_group 2;\n");
        } else if (i + 1 < NT) {
            asm volatile("cp.async.wait_group 1;\n");
        } else {
            asm volatile("cp.async.wait_group 0;\n");
        }
        __syncthreads();

        const unsigned* sb = sm + (i % NSTG) * STAGE;
#pragma unroll
        for (int ks = 0; ks < 2; ks++) {
            const int co = ks * 8;
            unsigned ah[2][4], al[2][4], bh[4][2], bl[4][2];
#pragma unroll
            for (int mi = 0; mi < 2; mi++) {
                ldsm_x4(ah[mi], sb + OFF_AH + (a_row + mi * 16) * RS + co + a_colu);
                ldsm_x4(al[mi], sb + OFF_AL + (a_row + mi * 16) * RS + co + a_colu);
            }
#pragma unroll
            for (int np = 0; np < 2; np++) {
                unsigned th[4], tl[4];
                ldsm_x4(th, sb + OFF_WH + (b_row + np * 16) * RS + co + b_colu);
                ldsm_x4(tl, sb + OFF_WL + (b_row + np * 16) * RS + co + b_colu);
                bh[2*np][0] = th[0]; bh[2*np][1] = th[1];
                bh[2*np+1][0] = th[2]; bh[2*np+1][1] = th[3];
                bl[2*np][0] = tl[0]; bl[2*np][1] = tl[1];
                bl[2*np+1][0] = tl[2]; bl[2*np+1][1] = tl[3];
            }
#pragma unroll
            for (int mi = 0; mi < 2; mi++)
#pragma unroll
                for (int ni = 0; ni < 4; ni++) {
                    mma16816h(cacc[mi][ni], al[mi], bh[ni]);
                    mma16816h(cacc[mi][ni], ah[mi], bl[ni]);
                    mma16816(acc[mi][ni], ah[mi], bh[ni]);
                }
        }
        __syncthreads();
    }

    if (mode == 2) {
#pragma unroll
        for (int mi = 0; mi < 2; mi++)
#pragma unroll
            for (int ni = 0; ni < 4; ni++) {
                float2 cA = h2f2(cacc[mi][ni][0]);
                float2 cB = h2f2(cacc[mi][ni][1]);
                float vv[4] = { acc[mi][ni][0] + cA.x, acc[mi][ni][1] + cA.y,
                                acc[mi][ni][2] + cB.x, acc[mi][ni][3] + cB.y };
                int row0 = m0 + wm + mi * 16 + gr;
                int col0 = n0 + wn + ni * 8 + tg * 2;
#pragma unroll
                for (int e = 0; e < 4; e++) {
                    int r = row0 + (e >> 1) * 8;
                    int c = col0 + (e & 1);
                    out2[(size_t)r * ldo + c] = vv[e];
                }
            }
    } else {
        // gate-interleaved cell epilogue: cols 4u+{0,1,2,3} = i,f,g,o
#pragma unroll
        for (int mi = 0; mi < 2; mi++)
#pragma unroll
            for (int ni = 0; ni < 4; ni++) {
                float2 cA = h2f2(cacc[mi][ni][0]);
                float2 cB = h2f2(cacc[mi][ni][1]);
                int r0 = m0 + wm + mi * 16 + gr;
                int cb = n0 + wn + ni * 8 + tg * 2;
                float v0 = acc[mi][ni][0] + cA.x + bias[cb];
                float v1 = acc[mi][ni][1] + cA.y + bias[cb + 1];
                float v2 = acc[mi][ni][2] + cB.x + bias[cb];
                float v3 = acc[mi][ni][3] + cB.y + bias[cb + 1];
                float p0 = __shfl_xor_sync(0xffffffffu, v0, 1);
                float p1 = __shfl_xor_sync(0xffffffffu, v1, 1);
                float p2 = __shfl_xor_sync(0xffffffffu, v2, 1);
                float p3 = __shfl_xor_sync(0xffffffffu, v3, 1);
                if (!(tg & 1)) {
                    int u = cb >> 2;
                    int i0 = r0 * Hn + u;
                    float cn = sigf(v1) * cst[i0] + sigf(v0) * tanhf(p0);
                    cst[i0] = cn;
                    float hn = sigf(p1) * tanhf(cn);
                    __half hv = __float2half_rn(hn);
                    Hh[i0] = hv; Hl[i0] = __float2half_rn(hn - __half2float(hv));
                    int i1 = i0 + 8 * Hn;
                    float cn2 = sigf(v3) * cst[i1] + sigf(v2) * tanhf(p2);
                    cst[i1] = cn2;
                    float hn2 = sigf(p3) * tanhf(cn2);
                    __half hv2 = __float2half_rn(hn2);
                    Hh[i1] = hv2; Hl[i1] = __float2half_rn(hn2 - __half2float(hv2));
                }
            }
    }
}

// ---------------- merged encode step: L1(k-1) on CTAs 0-127, L0(k) on 128-255
__global__ void __launch_bounds__(256) enc_step(int k)
{
    extern __shared__ unsigned sm[];
    int cta = blockIdx.x;
    if (cta < 128) {
        if (k < 1) return;
        int m0 = (cta >> 5) * BM, n0 = (cta & 31) * BN;
        gemm_core(sm, m0, n0, 0, 2048 / BK,
                  g_H0h[(k + 1) & 1], g_H0l[(k + 1) & 1], Hn, Hn,
                  g_H1h[k & 1], g_H1l[k & 1], Hn,
                  g_W1h, g_W1l, 2048, g_bp1, 0,
                  nullptr, 0, g_c1, g_H1h[(k + 1) & 1], g_H1l[(k + 1) & 1]);
    } else {
        if (k >= PREn) return;
        int c2 = cta - 128;
        int m0 = (c2 >> 5) * BM, n0 = (c2 & 31) * BN;
        const __half* xyh = g_XYh + (size_t)k * Bn * INn;
        const __half* xyl = g_XYl + (size_t)k * Bn * INn;
        gemm_core(sm, m0, n0, 0, 1280 / BK,
                  xyh, xyl, INn, INn,
                  g_H0h[(k + 1) & 1], g_H0l[(k + 1) & 1], Hn,
                  g_W0h, g_W0l, 1280, g_bp0, 0,
                  nullptr, 0, g_c0, g_H0h[k & 1], g_H0l[k & 1]);
    }
}

// ---------------- decode merged launch ---------------------------------------
// CTAs 0-127:  fc1p split-K (8 tiles) -> fc barrier -> fccomb (est) -> signal
// CTAs 128-255: wait for est signal -> full L0 gate GEMM (K=1280) + cell
// All fc CTAs (bid 0-127) are wave-1 resident (1 CTA/SM, 256-CTA launch), so
// the L0 CTAs' spin cannot deadlock: the producers always make progress.
__global__ void __launch_bounds__(256) dec_par(
    int t, const float* __restrict__ fc_b1, const float* __restrict__ fc_w2,
    const float* __restrict__ fc_b2, float* __restrict__ outp_t,
    __half* __restrict__ fxh, __half* __restrict__ fxl)
{
    extern __shared__ unsigned sm[];
    int cta = blockIdx.x;
    int tid = threadIdx.x;
    int rd = (t + 1) & 1;
    if (cta < 128) {
        // fc1 split-K x4: raw partials into g_t1p
        int ks = cta >> 5, rem = cta & 31;
        int m0 = ((rem >> 3) & 3) * BM, n0 = (rem & 7) * BN;
        gemm_core(sm, m0, n0, ks * 8, 8,
                  g_H1h[rd], g_H1l[rd], 1 << 30, Hn, nullptr, nullptr, Hn,
                  g_Wfh, g_Wfl, Hn, nullptr, 2,
                  g_t1p[ks], Hn, nullptr, nullptr, nullptr);

        // fc-group barrier (all 128 fc CTAs are wave-1 resident)
        __threadfence();
        __syncthreads();
        if (tid == 0) {
            atomicAdd(&g_fccnt[t], 1u);
            while (atomicAdd(&g_fccnt[t], 0u) < 128u) __nanosleep(40);
        }
        __syncthreads();
        __threadfence();

        // fccomb: 2 batch rows per CTA, staged in (now free) dynamic smem
        float* t1row = (float*)sm;
        int w = tid >> 5, lane = tid & 31;
#pragma unroll 1
        for (int rb = 0; rb < 2; rb++) {
            int b = cta * 2 + rb;
            for (int i = tid; i < Hn; i += 256) {
                int idx = b * Hn + i;
                float v = g_t1p[0][idx] + g_t1p[1][idx] + g_t1p[2][idx] + g_t1p[3][idx]
                        + fc_b1[i];
                t1row[i] = tanhf(v);
            }
            __syncthreads();
#pragma unroll 1
            for (int jj = 0; jj < 8; jj++) {
                int j = w * 8 + jj;
                const float* wrow = fc_w2 + (size_t)j * Hn;
                float s = 0.0f;
#pragma unroll 8
                for (int k2 = lane; k2 < Hn; k2 += 32) s += t1row[k2] * wrow[k2];
#pragma unroll
                for (int o = 16; o; o >>= 1) s += __shfl_xor_sync(0xffffffffu, s, o);
                if (lane == 0) {
                    float v = s + fc_b2[j] + g_est[b * YDn + j];
                    g_est[b * YDn + j] = v;
                    outp_t[b * YDn + j] = v;
                    __half hh = __float2half_rn(v);
                    int d = b * INn + XDn + j;
                    fxh[d] = hh;
                    fxl[d] = __float2half_rn(v - __half2float(hh));
                }
            }
            __syncthreads();
        }
        // signal: this CTA's est rows are in FX
        __threadfence();
        if (tid == 0) atomicAdd(&g_fcdone[t], 1u);
    } else {
        // wait for all est values (fc CTAs are resident and progressing)
        if (tid == 0) {
            while (atomicAdd(&g_fcdone[t], 0u) < 128u) __nanosleep(60);
        }
        __syncthreads();
        __threadfence();
        // full L0 gate GEMM (identical to the validated dec_l0) + cell epilogue
        int c2 = cta - 128;
        int m0 = (c2 >> 5) * BM, n0 = (c2 & 31) * BN;
        int wr = t & 1;
        gemm_core(sm, m0, n0, 0, 1280 / BK,
                  fxh, fxl, INn, INn, g_H0h[rd], g_H0l[rd], Hn,
                  g_W0h, g_W0l, 1280, g_bp0, 0,
                  nullptr, 0, g_c0, g_H0h[wr], g_H0l[wr]);
    }
}

// ---------------- decode L1 ---------------------------------------------------
__global__ void __launch_bounds__(256) dec_l1(int t)
{
    extern __shared__ unsigned sm[];
    int cta = blockIdx.x;
    int m0 = (cta >> 5) * BM, n0 = (cta & 31) * BN;
    int rd = (t + 1) & 1, wr = t & 1;
    gemm_core(sm, m0, n0, 0, 2048 / BK,
              g_H0h[wr], g_H0l[wr], Hn, Hn, g_H1h[rd], g_H1l[rd], Hn,
              g_W1h, g_W1l, 2048, g_bp1, 0,
              nullptr, 0, g_c1, g_H1h[wr], g_H1l[wr]);
}

// ---------------- packing kernels --------------------------------------------
__global__ void __launch_bounds__(256) split_kernel(
    const float* __restrict__ src, __half* __restrict__ dh, __half* __restrict__ dl,
    int w, int ldd, int off, int total, int remap)
{
    for (int idx = blockIdx.x * 256 + threadIdx.x; idx < total; idx += gridDim.x * 256) {
        int n = idx / w;
        int k = idx - n * w;
        int pr = remap ? (((n & 1023) << 2) | (n >> 10)) : n;
        float v = src[idx];
        __half h = __float2half_rn(v);
        int d = pr * ldd + off + k;
        dh[d] = h;
        dl[d] = __float2half_rn(v - __half2float(h));
    }
}

__global__ void __launch_bounds__(256) biaspack_kernel(
    const float* __restrict__ bi, const float* __restrict__ bh, float* __restrict__ op)
{
    int n = blockIdx.x * 256 + threadIdx.x;
    if (n < G4H) {
        int u = n & 1023, g = n >> 10;
        op[4 * u + g] = bi[n] + bh[n];
    }
}

// init: zero state buffers (buf 1 = "step -1"), est = pre_y[-1], counters
__global__ void __launch_bounds__(256) init_kernel(const float* __restrict__ pre_y)
{
    int i = blockIdx.x * 256 + threadIdx.x;
    if (i < Bn * Hn) {
        g_c0[i] = 0.0f; g_c1[i] = 0.0f;
        __half z = __float2half_rn(0.0f);
        g_H0h[1][i] = z; g_H0l[1][i] = z;
        g_H1h[1][i] = z; g_H1l[1][i] = z;
    }
    if (i < Bn * YDn) g_est[i] = pre_y[(PREn - 1) * Bn * YDn + i];
    if (i < FWDn) { g_fccnt[i] = 0u; g_fcdone[i] = 0u; }
}

// ---------------- launch -----------------------------------------------------
extern "C" void kernel_launch(void* const* d_in, const int* in_sizes, int n_in,
                              void* d_out, int out_size)
{
    const float* pre_x  = (const float*)d_in[0];
    const float* pre_y  = (const float*)d_in[1];
    const float* fwd_x  = (const float*)d_in[2];
    const float* w_ih0  = (const float*)d_in[3];
    const float* w_hh0  = (const float*)d_in[4];
    const float* b_ih0  = (const float*)d_in[5];
    const float* b_hh0  = (const float*)d_in[6];
    const float* w_ih1  = (const float*)d_in[7];
    const float* w_hh1  = (const float*)d_in[8];
    const float* b_ih1  = (const float*)d_in[9];
    const float* b_hh1  = (const float*)d_in[10];
    const float* fc_w1  = (const float*)d_in[11];
    const float* fc_b1  = (const float*)d_in[12];
    const float* fc_w2  = (const float*)d_in[13];
    const float* fc_b2  = (const float*)d_in[14];
    float* outp = (float*)d_out;

    cudaFuncSetAttribute(enc_step, cudaFuncAttributeMaxDynamicSharedMemorySize, SMEMB);
    cudaFuncSetAttribute(dec_par,  cudaFuncAttributeMaxDynamicSharedMemorySize, SMEMB);
    cudaFuncSetAttribute(dec_l1,   cudaFuncAttributeMaxDynamicSharedMemorySize, SMEMB);

    void *pv;
    #define SYM(name, var) cudaGetSymbolAddress(&pv, var); auto* name = (decltype(&var[0]))pv;
    SYM(W0h, g_W0h) SYM(W0l, g_W0l) SYM(W1h, g_W1h) SYM(W1l, g_W1l)
    SYM(Wfh, g_Wfh) SYM(Wfl, g_Wfl) SYM(bp0, g_bp0) SYM(bp1, g_bp1)
    SYM(XYh, g_XYh) SYM(XYl, g_XYl) SYM(FXh, g_FXh) SYM(FXl, g_FXl)
    #undef SYM

    dim3 blk(256);
    int sB = 2048;

    // one-time packing (gate-interleaved weights, hi/lo splits)
    split_kernel<<<sB, blk>>>(w_ih0, W0h, W0l, INn, 1280, 0,   G4H * INn, 1);
    split_kernel<<<sB, blk>>>(w_hh0, W0h, W0l, Hn,  1280, INn, G4H * Hn, 1);
    split_kernel<<<sB, blk>>>(w_ih1, W1h, W1l, Hn,  2048, 0,   G4H * Hn, 1);
    split_kernel<<<sB, blk>>>(w_hh1, W1h, W1l, Hn,  2048, Hn,  G4H * Hn, 1);
    split_kernel<<<sB, blk>>>(fc_w1, Wfh, Wfl, Hn,  1024, 0,   Hn * Hn, 0);
    split_kernel<<<sB, blk>>>(pre_x, XYh, XYl, XDn, INn, 0,    PREn * Bn * XDn, 0);
    split_kernel<<<sB, blk>>>(pre_y, XYh, XYl, YDn, INn, XDn,  PREn * Bn * YDn, 0);
    split_kernel<<<sB, blk>>>(fwd_x, FXh, FXl, XDn, INn, 0,    FWDn * Bn * XDn, 0);
    biaspack_kernel<<<16, blk>>>(b_ih0, b_hh0, bp0);
    biaspack_kernel<<<16, blk>>>(b_ih1, b_hh1, bp1);
    init_kernel<<<(Bn * Hn) / 256, blk>>>(pre_y);

    // ---------------- encode: merged L0(k) || L1(k-1), k = 0..PREn ----------
    for (int k = 0; k <= PREn; k++)
        enc_step<<<256, blk, SMEMB>>>(k);

    // ---------------- decode: 2 launches/step -------------------------------
    for (int t = 0; t < FWDn; t++) {
        __half* fxh = FXh + (size_t)t * Bn * INn;
        __half* fxl = FXl + (size_t)t * Bn * INn;
        dec_par<<<256, blk, SMEMB>>>(t, fc_b1, fc_w2, fc_b2,
                                     outp + (size_t)t * Bn * YDn, fxh, fxl);
        dec_l1<<<128, blk, SMEMB>>>(t);
    }
}

// round 17
// speedup vs baseline: 1.1582x; 1.1582x over previous
#include <cuda_runtime.h>
#include <cuda_fp16.h>
#include <math.h>
#include <stdint.h>

#define Bn   256
#define Hn   1024
#define XDn  192
#define YDn  64
#define INn  256
#define PREn 64
#define FWDn 48
#define G4H  4096

// ---------------- scratch (device globals; no allocations allowed) ----------
__device__ __half g_W0h[G4H * 1280], g_W0l[G4H * 1280];
__device__ __half g_W1h[G4H * 2048], g_W1l[G4H * 2048];
__device__ __half g_Wfh[Hn * Hn],    g_Wfl[Hn * Hn];
__device__ float  g_bp0[G4H], g_bp1[G4H];
__device__ __half g_XYh[PREn * Bn * INn], g_XYl[PREn * Bn * INn];
__device__ __half g_FXh[FWDn * Bn * INn], g_FXl[FWDn * Bn * INn];
__device__ __half g_H0h[2][Bn * Hn], g_H0l[2][Bn * Hn];
__device__ __half g_H1h[2][Bn * Hn], g_H1l[2][Bn * Hn];
__device__ float g_c0[Bn * Hn], g_c1[Bn * Hn];
__device__ float g_t1p[4][Bn * Hn], g_est[Bn * YDn];
__device__ float g_zp[Bn * G4H];          // decode L0 h-part partials
__device__ unsigned g_fccnt[FWDn];        // per-step fc-group barrier counters

// ---------------- helpers ----------------------------------------------------
// fast sigmoid/tanh via __expf (rel err ~1e-6; clamped to avoid inf/inf)
__device__ __forceinline__ float sigf(float x) {
    return __fdividef(1.0f, 1.0f + __expf(-x));
}
__device__ __forceinline__ float tanhfast(float x) {
    float xc = fminf(fmaxf(x, -15.0f), 15.0f);
    float e = __expf(2.0f * xc);
    return __fdividef(e - 1.0f, e + 1.0f);
}

__device__ __forceinline__ void cpa16(void* dst, const void* src) {
    unsigned d = (unsigned)__cvta_generic_to_shared(dst);
    asm volatile("cp.async.cg.shared.global [%0], [%1], 16;\n" :: "r"(d), "l"(src));
}

__device__ __forceinline__ void ldsm_x4(unsigned r[4], const unsigned* p) {
    unsigned addr = (unsigned)__cvta_generic_to_shared(p);
    asm volatile("ldmatrix.sync.aligned.m8n8.x4.shared.b16 {%0,%1,%2,%3}, [%4];\n"
        : "=r"(r[0]), "=r"(r[1]), "=r"(r[2]), "=r"(r[3]) : "r"(addr));
}

// fp32-accumulate HMMA (hi*hi term)
__device__ __forceinline__ void mma16816(float c[4], const unsigned a[4], const unsigned b[2]) {
    asm volatile(
        "mma.sync.aligned.m16n8k16.row.col.f32.f16.f16.f32 "
        "{%0,%1,%2,%3}, {%4,%5,%6,%7}, {%8,%9}, {%0,%1,%2,%3};\n"
        : "+f"(c[0]), "+f"(c[1]), "+f"(c[2]), "+f"(c[3])
        : "r"(a[0]), "r"(a[1]), "r"(a[2]), "r"(a[3]), "r"(b[0]), "r"(b[1]));
}

// fp16-accumulate HMMA (correction terms)
__device__ __forceinline__ void mma16816h(unsigned c[2], const unsigned a[4], const unsigned b[2]) {
    asm volatile(
        "mma.sync.aligned.m16n8k16.row.col.f16.f16.f16.f16 "
        "{%0,%1}, {%2,%3,%4,%5}, {%6,%7}, {%0,%1};\n"
        : "+r"(c[0]), "+r"(c[1])
        : "r"(a[0]), "r"(a[1]), "r"(a[2]), "r"(a[3]), "r"(b[0]), "r"(b[1]));
}

__device__ __forceinline__ float2 h2f2(unsigned u) {
    __half2 h = *reinterpret_cast<__half2*>(&u);
    return __half22float2(h);
}

// ---------------- fp16x3 GEMM core: 64x128, 3-stage (round-7 structure) -----
#define BM 64
#define BN 128
#define BK 32
#define RS 20
#define OFF_AH 0
#define OFF_AL (BM * RS)
#define OFF_WH (2 * BM * RS)
#define OFF_WL (2 * BM * RS + BN * RS)
#define STAGE  (2 * BM * RS + 2 * BN * RS)   // 7680 uints = 30720 B
#define NSTG   3
#define SMEMB  (NSTG * STAGE * 4)            // 92160 B

__device__ __forceinline__ void load_tile(
    unsigned* sm, int sbase, int k0, int m0, int n0, int tid,
    const __half* a0h, const __half* a0l, int w0, int lda0,
    const __half* a1h, const __half* a1l, int lda1,
    const __half* wgh, const __half* wgl, int ldw)
{
    const __half *ah, *al; int lda, koff;
    if (k0 < w0) { ah = a0h; al = a0l; lda = lda0; koff = k0; }
    else         { ah = a1h; al = a1l; lda = lda1; koff = k0 - w0; }
#pragma unroll
    for (int i = 0; i < 2; i++) {           // A: 512 16B chunks (hi+lo)
        int c = tid + (i << 8);
        int part = c >> 8;
        int row  = (c & 255) >> 2;
        int kc   = c & 3;
        const __half* src = (part ? al : ah) + (size_t)(m0 + row) * lda + koff + kc * 8;
        unsigned* dst = sm + sbase + (part ? OFF_AL : OFF_AH) + row * RS + kc * 4;
        cpa16(dst, src);
    }
#pragma unroll
    for (int i = 0; i < 4; i++) {           // W: 1024 16B chunks (hi+lo)
        int c = tid + (i << 8);
        int part = c >> 9;
        int row  = (c & 511) >> 2;
        int kc   = c & 3;
        const __half* src = (part ? wgl : wgh) + (size_t)(n0 + row) * ldw + k0 + kc * 8;
        unsigned* dst = sm + sbase + (part ? OFF_WL : OFF_WH) + row * RS + kc * 4;
        cpa16(dst, src);
    }
}

// mode 0: fused LSTM cell (gate-interleaved W); mode 2: raw acc -> out2[r*ldo+c]
// zinit: optional fp32 accumulator init from zinit[r*G4H + c]
__device__ __forceinline__ void gemm_core(
    unsigned* sm, int m0, int n0, int kt0, int NT,
    const __half* a0h, const __half* a0l, int w0, int lda0,
    const __half* a1h, const __half* a1l, int lda1,
    const __half* wgh, const __half* wgl, int ldw,
    const float* bias, int mode,
    float* out2, int ldo, const float* zinit,
    float* cst, __half* Hh, __half* Hl)
{
    const int tid  = threadIdx.x;
    const int warp = tid >> 5;
    const int lane = tid & 31;
    const int wm = (warp & 1) * 32;
    const int wn = (warp >> 1) * 32;
    const int gr = lane >> 2;
    const int tg = lane & 3;
    const int a_row  = wm + (lane & 15);
    const int a_colu = (lane >> 4) << 2;
    const int b_row  = wn + (lane & 7) + ((lane >> 4) << 3);
    const int b_colu = ((lane >> 3) & 1) << 2;

    float acc[2][4][4];
    unsigned cacc[2][4][2];
    if (zinit) {
#pragma unroll
        for (int mi = 0; mi < 2; mi++)
#pragma unroll
            for (int ni = 0; ni < 4; ni++) {
                int row0 = m0 + wm + mi * 16 + gr;
                int col0 = n0 + wn + ni * 8 + tg * 2;
                float2 z0 = *(const float2*)(zinit + (size_t)row0 * G4H + col0);
                float2 z1 = *(const float2*)(zinit + (size_t)(row0 + 8) * G4H + col0);
                acc[mi][ni][0] = z0.x; acc[mi][ni][1] = z0.y;
                acc[mi][ni][2] = z1.x; acc[mi][ni][3] = z1.y;
                cacc[mi][ni][0] = 0u; cacc[mi][ni][1] = 0u;
            }
    } else {
#pragma unroll
        for (int mi = 0; mi < 2; mi++)
#pragma unroll
            for (int ni = 0; ni < 4; ni++) {
#pragma unroll
                for (int e = 0; e < 4; e++) acc[mi][ni][e] = 0.0f;
                cacc[mi][ni][0] = 0u; cacc[mi][ni][1] = 0u;
            }
    }

    load_tile(sm, 0, kt0 * BK, m0, n0, tid, a0h, a0l, w0, lda0, a1h, a1l, lda1, wgh, wgl, ldw);
    asm volatile("cp.async.commit_group;\n");
    if (NT > 1) {
        load_tile(sm, STAGE, (kt0 + 1) * BK, m0, n0, tid, a0h, a0l, w0, lda0, a1h, a1l, lda1, wgh, wgl, ldw);
        asm volatile("cp.async.commit_group;\n");
    }

    for (int i = 0; i < NT; i++) {
        if (i + 2 < NT) {
            load_tile(sm, ((i + 2) % NSTG) * STAGE, (kt0 + i + 2) * BK, m0, n0, tid,
                      a0h, a0l, w0, lda0, a1h, a1l, lda1, wgh, wgl, ldw);
            asm volatile("cp.async.commit_group;\n");
            asm volatile("cp.async.wait_group 2;\n");
        } else if (i + 1 < NT) {
            asm volatile("cp.async.wait_group 1;\n");
        } else {
            asm volatile("cp.async.wait_group 0;\n");
        }
        __syncthreads();

        const unsigned* sb = sm + (i % NSTG) * STAGE;
#pragma unroll
        for (int ks = 0; ks < 2; ks++) {
            const int co = ks * 8;
            unsigned ah[2][4], al[2][4], bh[4][2], bl[4][2];
#pragma unroll
            for (int mi = 0; mi < 2; mi++) {
                ldsm_x4(ah[mi], sb + OFF_AH + (a_row + mi * 16) * RS + co + a_colu);
                ldsm_x4(al[mi], sb + OFF_AL + (a_row + mi * 16) * RS + co + a_colu);
            }
#pragma unroll
            for (int np = 0; np < 2; np++) {
                unsigned th[4], tl[4];
                ldsm_x4(th, sb + OFF_WH + (b_row + np * 16) * RS + co + b_colu);
                ldsm_x4(tl, sb + OFF_WL + (b_row + np * 16) * RS + co + b_colu);
                bh[2*np][0] = th[0]; bh[2*np][1] = th[1];
                bh[2*np+1][0] = th[2]; bh[2*np+1][1] = th[3];
                bl[2*np][0] = tl[0]; bl[2*np][1] = tl[1];
                bl[2*np+1][0] = tl[2]; bl[2*np+1][1] = tl[3];
            }
#pragma unroll
            for (int mi = 0; mi < 2; mi++)
#pragma unroll
                for (int ni = 0; ni < 4; ni++) {
                    mma16816h(cacc[mi][ni], al[mi], bh[ni]);
                    mma16816h(cacc[mi][ni], ah[mi], bl[ni]);
                    mma16816(acc[mi][ni], ah[mi], bh[ni]);
                }
        }
        __syncthreads();
    }

    if (mode == 2) {
#pragma unroll
        for (int mi = 0; mi < 2; mi++)
#pragma unroll
            for (int ni = 0; ni < 4; ni++) {
                float2 cA = h2f2(cacc[mi][ni][0]);
                float2 cB = h2f2(cacc[mi][ni][1]);
                float vv[4] = { acc[mi][ni][0] + cA.x, acc[mi][ni][1] + cA.y,
                                acc[mi][ni][2] + cB.x, acc[mi][ni][3] + cB.y };
                int row0 = m0 + wm + mi * 16 + gr;
                int col0 = n0 + wn + ni * 8 + tg * 2;
#pragma unroll
                for (int e = 0; e < 4; e++) {
                    int r = row0 + (e >> 1) * 8;
                    int c = col0 + (e & 1);
                    out2[(size_t)r * ldo + c] = vv[e];
                }
            }
    } else {
        // gate-interleaved cell epilogue: cols 4u+{0,1,2,3} = i,f,g,o
#pragma unroll
        for (int mi = 0; mi < 2; mi++)
#pragma unroll
            for (int ni = 0; ni < 4; ni++) {
                float2 cA = h2f2(cacc[mi][ni][0]);
                float2 cB = h2f2(cacc[mi][ni][1]);
                int r0 = m0 + wm + mi * 16 + gr;
                int cb = n0 + wn + ni * 8 + tg * 2;
                float v0 = acc[mi][ni][0] + cA.x + bias[cb];
                float v1 = acc[mi][ni][1] + cA.y + bias[cb + 1];
                float v2 = acc[mi][ni][2] + cB.x + bias[cb];
                float v3 = acc[mi][ni][3] + cB.y + bias[cb + 1];
                float p0 = __shfl_xor_sync(0xffffffffu, v0, 1);
                float p1 = __shfl_xor_sync(0xffffffffu, v1, 1);
                float p2 = __shfl_xor_sync(0xffffffffu, v2, 1);
                float p3 = __shfl_xor_sync(0xffffffffu, v3, 1);
                if (!(tg & 1)) {
                    int u = cb >> 2;
                    int i0 = r0 * Hn + u;
                    float cn = sigf(v1) * cst[i0] + sigf(v0) * tanhfast(p0);
                    cst[i0] = cn;
                    float hn = sigf(p1) * tanhfast(cn);
                    __half hv = __float2half_rn(hn);
                    Hh[i0] = hv; Hl[i0] = __float2half_rn(hn - __half2float(hv));
                    int i1 = i0 + 8 * Hn;
                    float cn2 = sigf(v3) * cst[i1] + sigf(v2) * tanhfast(p2);
                    cst[i1] = cn2;
                    float hn2 = sigf(p3) * tanhfast(cn2);
                    __half hv2 = __float2half_rn(hn2);
                    Hh[i1] = hv2; Hl[i1] = __float2half_rn(hn2 - __half2float(hv2));
                }
            }
    }
}

// ---------------- merged encode step: L1(k-1) on CTAs 0-127, L0(k) on 128-255
__global__ void __launch_bounds__(256) enc_step(int k)
{
    extern __shared__ unsigned sm[];
    int cta = blockIdx.x;
    if (cta < 128) {
        if (k < 1) return;
        int m0 = (cta >> 5) * BM, n0 = (cta & 31) * BN;
        gemm_core(sm, m0, n0, 0, 2048 / BK,
                  g_H0h[(k + 1) & 1], g_H0l[(k + 1) & 1], Hn, Hn,
                  g_H1h[k & 1], g_H1l[k & 1], Hn,
                  g_W1h, g_W1l, 2048, g_bp1, 0,
                  nullptr, 0, nullptr, g_c1, g_H1h[(k + 1) & 1], g_H1l[(k + 1) & 1]);
    } else {
        if (k >= PREn) return;
        int c2 = cta - 128;
        int m0 = (c2 >> 5) * BM, n0 = (c2 & 31) * BN;
        const __half* xyh = g_XYh + (size_t)k * Bn * INn;
        const __half* xyl = g_XYl + (size_t)k * Bn * INn;
        gemm_core(sm, m0, n0, 0, 1280 / BK,
                  xyh, xyl, INn, INn,
                  g_H0h[(k + 1) & 1], g_H0l[(k + 1) & 1], Hn,
                  g_W0h, g_W0l, 1280, g_bp0, 0,
                  nullptr, 0, nullptr, g_c0, g_H0h[k & 1], g_H0l[k & 1]);
    }
}

// ---------------- decode merged launch ---------------------------------------
// CTAs 0-127:  fc1p split-K (8 tiles) -> fc-group barrier -> fccomb (2 rows/CTA)
// CTAs 128-255: dec_l0a h-part (K=[256,1280)) -> raw partials into g_zp
__global__ void __launch_bounds__(256) dec_par(
    int t, const float* __restrict__ fc_b1, const float* __restrict__ fc_w2,
    const float* __restrict__ fc_b2, float* __restrict__ outp_t,
    __half* __restrict__ fxh, __half* __restrict__ fxl)
{
    extern __shared__ unsigned sm[];
    int cta = blockIdx.x;
    int tid = threadIdx.x;
    int rd = (t + 1) & 1;
    if (cta < 128) {
        // fc1 split-K x4: raw partials into g_t1p
        int ks = cta >> 5, rem = cta & 31;
        int m0 = ((rem >> 3) & 3) * BM, n0 = (rem & 7) * BN;
        gemm_core(sm, m0, n0, ks * 8, 8,
                  g_H1h[rd], g_H1l[rd], 1 << 30, Hn, nullptr, nullptr, Hn,
                  g_Wfh, g_Wfl, Hn, nullptr, 2,
                  g_t1p[ks], Hn, nullptr, nullptr, nullptr, nullptr);

        // fc-group barrier (CTAs 0-127 are all wave-1 resident; spin is safe)
        __threadfence();
        __syncthreads();
        if (tid == 0) {
            atomicAdd(&g_fccnt[t], 1u);
            while (atomicAdd(&g_fccnt[t], 0u) < 128u) __nanosleep(40);
        }
        __syncthreads();
        __threadfence();

        // fccomb: 2 batch rows per CTA, staged in (now free) dynamic smem
        float* t1row = (float*)sm;
        int w = tid >> 5, lane = tid & 31;
#pragma unroll 1
        for (int rb = 0; rb < 2; rb++) {
            int b = cta * 2 + rb;
            for (int i = tid; i < Hn; i += 256) {
                int idx = b * Hn + i;
                float v = g_t1p[0][idx] + g_t1p[1][idx] + g_t1p[2][idx] + g_t1p[3][idx]
                        + fc_b1[i];
                t1row[i] = tanhfast(v);
            }
            __syncthreads();
#pragma unroll 1
            for (int jj = 0; jj < 8; jj++) {
                int j = w * 8 + jj;
                const float* wrow = fc_w2 + (size_t)j * Hn;
                float s = 0.0f;
#pragma unroll 8
                for (int k2 = lane; k2 < Hn; k2 += 32) s += t1row[k2] * wrow[k2];
#pragma unroll
                for (int o = 16; o; o >>= 1) s += __shfl_xor_sync(0xffffffffu, s, o);
                if (lane == 0) {
                    float v = s + fc_b2[j] + g_est[b * YDn + j];
                    g_est[b * YDn + j] = v;
                    outp_t[b * YDn + j] = v;
                    __half hh = __float2half_rn(v);
                    int d = b * INn + XDn + j;
                    fxh[d] = hh;
                    fxl[d] = __float2half_rn(v - __half2float(hh));
                }
            }
            __syncthreads();
        }
    } else {
        // dec_l0a: h0 part of L0 gates (K = [256,1280)), raw partials into g_zp
        int c2 = cta - 128;
        int m0 = (c2 >> 5) * BM, n0 = (c2 & 31) * BN;
        gemm_core(sm, m0, n0, 8, 32,
                  g_FXh, g_FXl, INn, INn, g_H0h[rd], g_H0l[rd], Hn,
                  g_W0h, g_W0l, 1280, nullptr, 2,
                  g_zp, G4H, nullptr, nullptr, nullptr, nullptr);
    }
}

// ---------------- dec_l0b: input+est part (K=[0,256)) + acc init + cell ------
__global__ void __launch_bounds__(256) dec_l0b(int t)
{
    extern __shared__ unsigned sm[];
    int cta = blockIdx.x;
    int m0 = (cta >> 5) * BM, n0 = (cta & 31) * BN;
    int rd = (t + 1) & 1, wr = t & 1;
    const __half* fxh = g_FXh + (size_t)t * Bn * INn;
    const __half* fxl = g_FXl + (size_t)t * Bn * INn;
    gemm_core(sm, m0, n0, 0, 8,
              fxh, fxl, INn, INn, g_H0h[rd], g_H0l[rd], Hn,
              g_W0h, g_W0l, 1280, g_bp0, 0,
              nullptr, 0, g_zp, g_c0, g_H0h[wr], g_H0l[wr]);
}

// ---------------- decode L1 ---------------------------------------------------
__global__ void __launch_bounds__(256) dec_l1(int t)
{
    extern __shared__ unsigned sm[];
    int cta = blockIdx.x;
    int m0 = (cta >> 5) * BM, n0 = (cta & 31) * BN;
    int rd = (t + 1) & 1, wr = t & 1;
    gemm_core(sm, m0, n0, 0, 2048 / BK,
              g_H0h[wr], g_H0l[wr], Hn, Hn, g_H1h[rd], g_H1l[rd], Hn,
              g_W1h, g_W1l, 2048, g_bp1, 0,
              nullptr, 0, nullptr, g_c1, g_H1h[wr], g_H1l[wr]);
}

// ---------------- packing kernels --------------------------------------------
__global__ void __launch_bounds__(256) split_kernel(
    const float* __restrict__ src, __half* __restrict__ dh, __half* __restrict__ dl,
    int w, int ldd, int off, int total, int remap)
{
    for (int idx = blockIdx.x * 256 + threadIdx.x; idx < total; idx += gridDim.x * 256) {
        int n = idx / w;
        int k = idx - n * w;
        int pr = remap ? (((n & 1023) << 2) | (n >> 10)) : n;
        float v = src[idx];
        __half h = __float2half_rn(v);
        int d = pr * ldd + off + k;
        dh[d] = h;
        dl[d] = __float2half_rn(v - __half2float(h));
    }
}

__global__ void __launch_bounds__(256) biaspack_kernel(
    const float* __restrict__ bi, const float* __restrict__ bh, float* __restrict__ op)
{
    int n = blockIdx.x * 256 + threadIdx.x;
    if (n < G4H) {
        int u = n & 1023, g = n >> 10;
        op[4 * u + g] = bi[n] + bh[n];
    }
}

// init: zero state buffers (buf 1 = "step -1"), est = pre_y[-1], fc counters
__global__ void __launch_bounds__(256) init_kernel(const float* __restrict__ pre_y)
{
    int i = blockIdx.x * 256 + threadIdx.x;
    if (i < Bn * Hn) {
        g_c0[i] = 0.0f; g_c1[i] = 0.0f;
        __half z = __float2half_rn(0.0f);
        g_H0h[1][i] = z; g_H0l[1][i] = z;
        g_H1h[1][i] = z; g_H1l[1][i] = z;
    }
    if (i < Bn * YDn) g_est[i] = pre_y[(PREn - 1) * Bn * YDn + i];
    if (i < FWDn) g_fccnt[i] = 0u;
}

// ---------------- launch -----------------------------------------------------
extern "C" void kernel_launch(void* const* d_in, const int* in_sizes, int n_in,
                              void* d_out, int out_size)
{
    const float* pre_x  = (const float*)d_in[0];
    const float* pre_y  = (const float*)d_in[1];
    const float* fwd_x  = (const float*)d_in[2];
    const float* w_ih0  = (const float*)d_in[3];
    const float* w_hh0  = (const float*)d_in[4];
    const float* b_ih0  = (const float*)d_in[5];
    const float* b_hh0  = (const float*)d_in[6];
    const float* w_ih1  = (const float*)d_in[7];
    const float* w_hh1  = (const float*)d_in[8];
    const float* b_ih1  = (const float*)d_in[9];
    const float* b_hh1  = (const float*)d_in[10];
    const float* fc_w1  = (const float*)d_in[11];
    const float* fc_b1  = (const float*)d_in[12];
    const float* fc_w2  = (const float*)d_in[13];
    const float* fc_b2  = (const float*)d_in[14];
    float* outp = (float*)d_out;

    cudaFuncSetAttribute(enc_step, cudaFuncAttributeMaxDynamicSharedMemorySize, SMEMB);
    cudaFuncSetAttribute(dec_par,  cudaFuncAttributeMaxDynamicSharedMemorySize, SMEMB);
    cudaFuncSetAttribute(dec_l0b,  cudaFuncAttributeMaxDynamicSharedMemorySize, SMEMB);
    cudaFuncSetAttribute(dec_l1,   cudaFuncAttributeMaxDynamicSharedMemorySize, SMEMB);

    void *pv;
    #define SYM(name, var) cudaGetSymbolAddress(&pv, var); auto* name = (decltype(&var[0]))pv;
    SYM(W0h, g_W0h) SYM(W0l, g_W0l) SYM(W1h, g_W1h) SYM(W1l, g_W1l)
    SYM(Wfh, g_Wfh) SYM(Wfl, g_Wfl) SYM(bp0, g_bp0) SYM(bp1, g_bp1)
    SYM(XYh, g_XYh) SYM(XYl, g_XYl) SYM(FXh, g_FXh) SYM(FXl, g_FXl)
    #undef SYM

    dim3 blk(256);
    int sB = 2048;

    // one-time packing (gate-interleaved weights, hi/lo splits)
    split_kernel<<<sB, blk>>>(w_ih0, W0h, W0l, INn, 1280, 0,   G4H * INn, 1);
    split_kernel<<<sB, blk>>>(w_hh0, W0h, W0l, Hn,  1280, INn, G4H * Hn, 1);
    split_kernel<<<sB, blk>>>(w_ih1, W1h, W1l, Hn,  2048, 0,   G4H * Hn, 1);
    split_kernel<<<sB, blk>>>(w_hh1, W1h, W1l, Hn,  2048, Hn,  G4H * Hn, 1);
    split_kernel<<<sB, blk>>>(fc_w1, Wfh, Wfl, Hn,  1024, 0,   Hn * Hn, 0);
    split_kernel<<<sB, blk>>>(pre_x, XYh, XYl, XDn, INn, 0,    PREn * Bn * XDn, 0);
    split_kernel<<<sB, blk>>>(pre_y, XYh, XYl, YDn, INn, XDn,  PREn * Bn * YDn, 0);
    split_kernel<<<sB, blk>>>(fwd_x, FXh, FXl, XDn, INn, 0,    FWDn * Bn * XDn, 0);
    biaspack_kernel<<<16, blk>>>(b_ih0, b_hh0, bp0);
    biaspack_kernel<<<16, blk>>>(b_ih1, b_hh1, bp1);
    init_kernel<<<(Bn * Hn) / 256, blk>>>(pre_y);

    // ---------------- encode: merged L0(k) || L1(k-1), k = 0..PREn ----------
    for (int k = 0; k <= PREn; k++)
        enc_step<<<256, blk, SMEMB>>>(k);

    // ---------------- decode: 3 launches/step -------------------------------
    for (int t = 0; t < FWDn; t++) {
        __half* fxh = FXh + (size_t)t * Bn * INn;
        __half* fxl = FXl + (size_t)t * Bn * INn;
        dec_par<<<256, blk, SMEMB>>>(t, fc_b1, fc_w2, fc_b2,
                                     outp + (size_t)t * Bn * YDn, fxh, fxl);
        dec_l0b<<<128, blk, SMEMB>>>(t);
        dec_l1<<<128, blk, SMEMB>>>(t);
    }
}